// round 10
// baseline (speedup 1.0000x reference)
#include <cuda_runtime.h>

// RNN: h_{s+1} = tanh(X[s]*W_ih^T + b_ih + b_hh + h_s @ W_hh^T); y_s = h_{s+1}·W_out + b_out
// SEQ=512, BATCH=4096, IN_DIM=1, HID=30.
//
// R10: register-resident recurrence. Wall = 512 x S (per-elem step latency;
// issue never saturated), and S was dominated by the STS->WARPSYNC->LDS round
// trip through L1tex. Replaced by SHFL gather: lane r's tanh outputs (t0,t1)
// ARE h[2r],h[2r+1]; next step gathers 15 pairs via __shfl_sync with
// src = ehalf*16+k (both half-warps gather their own elem in the same instr).
// No smem, no syncwarp, no double buffer. Everything else = R9 (proven):
// lanes 0-15 elem A / 16-31 elem B; lane r owns rows {2r,2r+1}, K-packed f32x2
// weights; r=15 owns unscaled W_out/b_out readout row (its pre0 at step s is
// y[s-1]; shift-store + epilogue). Real rows pre-scaled by 2*log2(e) so
// tanh = 1 - 2*rcp(ex2(acc)+1). Branch-free body (predicated STG, clamped
// prefetch). rel_err ~6e-7 established.

#define SEQ   512
#define BATCH 4096
#define HID   30

typedef unsigned long long u64;

__device__ __forceinline__ u64 pack2(float lo, float hi) {
    u64 r;
    asm("mov.b64 %0, {%1, %2};" : "=l"(r) : "f"(lo), "f"(hi));
    return r;
}
__device__ __forceinline__ void unpack2(u64 v, float& a, float& b) {
    asm("mov.b64 {%0, %1}, %2;" : "=f"(a), "=f"(b) : "l"(v));
}
__device__ __forceinline__ u64 fma2(u64 a, u64 b, u64 c) {
    u64 d;
    asm("fma.rn.f32x2 %0, %1, %2, %3;" : "=l"(d) : "l"(a), "l"(b), "l"(c));
    return d;
}
__device__ __forceinline__ u64 add2(u64 a, u64 b) {
    u64 d;
    asm("add.rn.f32x2 %0, %1, %2;" : "=l"(d) : "l"(a), "l"(b));
    return d;
}
__device__ __forceinline__ float ex2f(float x) {
    float t; asm("ex2.approx.f32 %0, %1;" : "=f"(t) : "f"(x)); return t;
}
__device__ __forceinline__ float rcpf(float x) {
    float t; asm("rcp.approx.f32 %0, %1;" : "=f"(t) : "f"(x)); return t;
}
__device__ __forceinline__ void st_pred(unsigned p, float* ptr, float v) {
    asm volatile("{\n\t.reg .pred q;\n\tsetp.ne.u32 q, %0, 0;\n\t"
                 "@q st.global.f32 [%1], %2;\n\t}"
                 :: "r"(p), "l"(ptr), "f"(v) : "memory");
}

__global__ void __launch_bounds__(64) rnn_tanh_kernel(
    const float* __restrict__ X,      // [SEQ, BATCH]
    const float* __restrict__ W_ih,   // [HID, 1]
    const float* __restrict__ W_hh,   // [HID, HID]
    const float* __restrict__ b_ih,   // [HID]
    const float* __restrict__ b_hh,   // [HID]
    const float* __restrict__ W_out,  // [1, HID]
    const float* __restrict__ b_out,  // [1]
    float* __restrict__ Y)            // [SEQ, BATCH]
{
    const int lane  = threadIdx.x & 31;
    const int wip   = threadIdx.x >> 5;
    const int gw    = blockIdx.x * 2 + wip;      // 0..2047
    const int r     = lane & 15;
    const int base  = lane & 16;                 // shuffle base: 0 or 16

    const float C = 2.8853900817779268f;         // 2*log2(e)

    // Lane's two rows, K-packed over pairs k=0..14 (no pad needed: shuffles
    // only source lanes 0..14 of each half).
    u64 W0[15], W1[15];
    float bias0 = 0.f, bias1 = 0.f, wih0 = 0.f, wih1 = 0.f;
    if (r < 15) {
        const int R0 = 2 * r, R1 = 2 * r + 1;
        #pragma unroll
        for (int k = 0; k < 15; k++) {
            W0[k] = pack2(W_hh[R0 * HID + 2 * k] * C, W_hh[R0 * HID + 2 * k + 1] * C);
            W1[k] = pack2(W_hh[R1 * HID + 2 * k] * C, W_hh[R1 * HID + 2 * k + 1] * C);
        }
        wih0  = W_ih[R0] * C;              wih1  = W_ih[R1] * C;
        bias0 = (b_ih[R0] + b_hh[R0]) * C; bias1 = (b_ih[R1] + b_hh[R1]) * C;
    } else {
        #pragma unroll
        for (int k = 0; k < 15; k++) {
            W0[k] = pack2(W_out[2 * k], W_out[2 * k + 1]);
            W1[k] = 0ull;
        }
        bias0 = b_out[0];
    }

    const int e = 2 * gw + ((lane >> 4) & 1);    // this lane's batch elem
    const float* __restrict__ xp = X + e;
    float* ym = Y + e - BATCH;                   // y[s-1] cursor
    const unsigned is_out = (r == 15) ? 1u : 0u;

    // X prefetch pipeline, depth 3.
    float xf0 = xp[0];
    float xf1 = xp[BATCH];
    float xf2 = xp[2 * BATCH];

    // Register-resident h: lane r holds h[2r] (t0) and h[2r+1] (t1).
    float t0 = 0.f, t1 = 0.f;

    #pragma unroll 2
    for (int s = 0; s < SEQ; ++s) {
        const float x = xf0;
        xf0 = xf1; xf1 = xf2;
        int nidx = s + 3; nidx = nidx < SEQ - 1 ? nidx : SEQ - 1;
        xf2 = xp[nidx * BATCH];

        // Gather h via 15 pair-broadcast shuffles; 4 independent fma2 chains.
        u64 c0a = pack2(bias0, 0.f), c0b = 0ull;
        u64 c1a = pack2(bias1, 0.f), c1b = 0ull;
        #pragma unroll
        for (int k = 0; k < 15; k++) {
            const float lo = __shfl_sync(0xffffffffu, t0, base + k);
            const float hi = __shfl_sync(0xffffffffu, t1, base + k);
            const u64 p = pack2(lo, hi);
            if (k & 1) {
                c0b = fma2(p, W0[k], c0b);
                c1b = fma2(p, W1[k], c1b);
            } else {
                c0a = fma2(p, W0[k], c0a);
                c1a = fma2(p, W1[k], c1a);
            }
        }
        float u, v, w, z;
        unpack2(add2(c0a, c0b), u, v);
        unpack2(add2(c1a, c1b), w, z);
        const float pre0 = __fmaf_rn(x, wih0, u + v);
        const float pre1 = __fmaf_rn(x, wih1, w + z);

        // Readout lane: pre0 == y[s-1]. Predicated STG, no branch.
        st_pred(is_out & (unsigned)(s > 0), ym, pre0);
        ym += BATCH;

        // tanh (inputs pre-scaled by 2log2e on real rows): 1 - 2/(ex2+1).
        // r==15 produces finite garbage; never sourced by shuffles (k<=14).
        t0 = __fmaf_rn(-2.f, rcpf(ex2f(pre0) + 1.f), 1.f);
        t1 = __fmaf_rn(-2.f, rcpf(ex2f(pre1) + 1.f), 1.f);
    }

    // Epilogue: y[SEQ-1] from the final state (ym points at row SEQ-1).
    {
        u64 c0a = pack2(bias0, 0.f), c0b = 0ull;
        #pragma unroll
        for (int k = 0; k < 15; k++) {
            const float lo = __shfl_sync(0xffffffffu, t0, base + k);
            const float hi = __shfl_sync(0xffffffffu, t1, base + k);
            const u64 p = pack2(lo, hi);
            if (k & 1) c0b = fma2(p, W0[k], c0b);
            else       c0a = fma2(p, W0[k], c0a);
        }
        float u, v;
        unpack2(add2(c0a, c0b), u, v);
        st_pred(is_out, ym, u + v);
    }
}

extern "C" void kernel_launch(void* const* d_in, const int* in_sizes, int n_in,
                              void* d_out, int out_size) {
    const float* X     = (const float*)d_in[0];
    const float* W_ih  = (const float*)d_in[1];
    const float* W_hh  = (const float*)d_in[2];
    const float* b_ih  = (const float*)d_in[3];
    const float* b_hh  = (const float*)d_in[4];
    const float* W_out = (const float*)d_in[5];
    const float* b_out = (const float*)d_in[6];
    float* Y = (float*)d_out;

    // 2048 warps (2 elems each) in 64-thread blocks over all 148 SMs.
    rnn_tanh_kernel<<<1024, 64>>>(X, W_ih, W_hh, b_ih, b_hh, W_out, b_out, Y);
}

// round 12
// speedup vs baseline: 1.1780x; 1.1780x over previous
#include <cuda_runtime.h>

// RNN: h_{s+1} = tanh(X[s]*W_ih^T + b_ih + b_hh + h_s @ W_hh^T); y_s = h_{s+1}·W_out + b_out
// SEQ=512, BATCH=4096, IN_DIM=1, HID=30.
//
// R12 = R11 resubmitted (R11 bench was an infra failure: container died; no
// timing/correctness signal was produced). Single-variable experiment vs R9
// (best, 182.7us): re-block 64-thr -> 128-thr blocks. Warps map to SMSPs by
// (warp-id-in-block % 4); 64-thr blocks put every warp on SMSP 0/1, idling
// half the schedulers. 4 warps/block -> one warp per SMSP per block.
// Everything else identical to R9:
// - lanes 0-15 elem A / 16-31 elem B; lane r owns rows {2r,2r+1}, K-packed
//   f32x2 weights; r=15 owns unscaled W_out/b_out readout row.
// - h in warp-private smem, 8 LDS.128 per step, STS.64 writeback, syncwarp.
// - branch-free body: predicated STG for y[s-1], clamped X prefetch (depth 3),
//   unconditional pad-pair STS (zero weights).
// - real rows pre-scaled by 2*log2(e): tanh = 1 - 2*rcp(ex2(acc)+1).
// - readout: r=15's pre0 at step s IS y[s-1]; epilogue emits y[SEQ-1].

#define SEQ   512
#define BATCH 4096
#define HID   30

typedef unsigned long long u64;

__device__ __forceinline__ u64 pack2(float lo, float hi) {
    u64 r;
    asm("mov.b64 %0, {%1, %2};" : "=l"(r) : "f"(lo), "f"(hi));
    return r;
}
__device__ __forceinline__ void unpack2(u64 v, float& a, float& b) {
    asm("mov.b64 {%0, %1}, %2;" : "=f"(a), "=f"(b) : "l"(v));
}
__device__ __forceinline__ u64 fma2(u64 a, u64 b, u64 c) {
    u64 d;
    asm("fma.rn.f32x2 %0, %1, %2, %3;" : "=l"(d) : "l"(a), "l"(b), "l"(c));
    return d;
}
__device__ __forceinline__ u64 add2(u64 a, u64 b) {
    u64 d;
    asm("add.rn.f32x2 %0, %1, %2;" : "=l"(d) : "l"(a), "l"(b));
    return d;
}
__device__ __forceinline__ float ex2f(float x) {
    float t; asm("ex2.approx.f32 %0, %1;" : "=f"(t) : "f"(x)); return t;
}
__device__ __forceinline__ float rcpf(float x) {
    float t; asm("rcp.approx.f32 %0, %1;" : "=f"(t) : "f"(x)); return t;
}
// Predicated store: guaranteed @q STG, no BSSY/BSYNC convergence stack.
__device__ __forceinline__ void st_pred(unsigned p, float* ptr, float v) {
    asm volatile("{\n\t.reg .pred q;\n\tsetp.ne.u32 q, %0, 0;\n\t"
                 "@q st.global.f32 [%1], %2;\n\t}"
                 :: "r"(p), "l"(ptr), "f"(v) : "memory");
}

__global__ void __launch_bounds__(128) rnn_tanh_kernel(
    const float* __restrict__ X,      // [SEQ, BATCH]
    const float* __restrict__ W_ih,   // [HID, 1]
    const float* __restrict__ W_hh,   // [HID, HID]
    const float* __restrict__ b_ih,   // [HID]
    const float* __restrict__ b_hh,   // [HID]
    const float* __restrict__ W_out,  // [1, HID]
    const float* __restrict__ b_out,  // [1]
    float* __restrict__ Y)            // [SEQ, BATCH]
{
    // [warp][buf][elem-half][K-pair]; pair 15 = pad (zero weights multiply it).
    __shared__ __align__(16) u64 hbuf[4][2][2][16];

    const int lane  = threadIdx.x & 31;
    const int wip   = threadIdx.x >> 5;          // 0..3 -> SMSP 0..3
    const int gw    = blockIdx.x * 4 + wip;      // 0..2047
    const int r     = lane & 15;
    const int ehalf = lane >> 4;

    const float C = 2.8853900817779268f;         // 2*log2(e)

    u64 W0[16], W1[16];
    float bias0 = 0.f, bias1 = 0.f, wih0 = 0.f, wih1 = 0.f;
    if (r < 15) {
        const int R0 = 2 * r, R1 = 2 * r + 1;
        #pragma unroll
        for (int k = 0; k < 15; k++) {
            W0[k] = pack2(W_hh[R0 * HID + 2 * k] * C, W_hh[R0 * HID + 2 * k + 1] * C);
            W1[k] = pack2(W_hh[R1 * HID + 2 * k] * C, W_hh[R1 * HID + 2 * k + 1] * C);
        }
        W0[15] = 0ull; W1[15] = 0ull;
        wih0  = W_ih[R0] * C;              wih1  = W_ih[R1] * C;
        bias0 = (b_ih[R0] + b_hh[R0]) * C; bias1 = (b_ih[R1] + b_hh[R1]) * C;
    } else {
        #pragma unroll
        for (int k = 0; k < 15; k++) {
            W0[k] = pack2(W_out[2 * k], W_out[2 * k + 1]);
            W1[k] = 0ull;
        }
        W0[15] = 0ull; W1[15] = 0ull;
        bias0 = b_out[0];
    }

    hbuf[wip][0][ehalf][r] = 0ull;
    hbuf[wip][1][ehalf][r] = 0ull;
    __syncwarp();

    const int e = 2 * gw + ehalf;                // this lane's batch elem
    const float* __restrict__ xp = X + e;
    float* ym = Y + e - BATCH;                   // y[s-1] cursor (s=0 masked off)
    const unsigned is_out = (r == 15) ? 1u : 0u;

    // X prefetch pipeline, depth 3 (2 distinct addrs/warp -> dedup'd LDG).
    float xf0 = xp[0];
    float xf1 = xp[BATCH];
    float xf2 = xp[2 * BATCH];

    int cur = 0;
    #pragma unroll 2
    for (int s = 0; s < SEQ; ++s) {
        const float x = xf0;
        xf0 = xf1; xf1 = xf2;
        int nidx = s + 3; nidx = nidx < SEQ - 1 ? nidx : SEQ - 1;  // clamp, no branch
        xf2 = xp[nidx * BATCH];

        // 8 LDS.128 of this elem's h; 4 independent fma2 chains (2 rows x 2).
        const ulonglong2* __restrict__ hp =
            reinterpret_cast<const ulonglong2*>(&hbuf[wip][cur][ehalf][0]);
        u64 c0a = pack2(bias0, 0.f), c0b = 0ull;
        u64 c1a = pack2(bias1, 0.f), c1b = 0ull;
        #pragma unroll
        for (int i = 0; i < 8; i++) {
            ulonglong2 hv = hp[i];
            c0a = fma2(hv.x, W0[2 * i],     c0a);
            c0b = fma2(hv.y, W0[2 * i + 1], c0b);
            c1a = fma2(hv.x, W1[2 * i],     c1a);
            c1b = fma2(hv.y, W1[2 * i + 1], c1b);
        }
        float u, v, w, z;
        unpack2(add2(c0a, c0b), u, v);
        unpack2(add2(c1a, c1b), w, z);
        const float pre0 = __fmaf_rn(x, wih0, u + v);
        const float pre1 = __fmaf_rn(x, wih1, w + z);

        // y[s-1] = pre0 on readout lanes; predicated STG, no branch.
        st_pred(is_out & (unsigned)(s > 0), ym, pre0);
        ym += BATCH;

        // tanh: inputs pre-scaled by 2log2e on real rows -> 1 - 2/(ex2+1).
        const float t0 = __fmaf_rn(-2.f, rcpf(ex2f(pre0) + 1.f), 1.f);
        const float t1 = __fmaf_rn(-2.f, rcpf(ex2f(pre1) + 1.f), 1.f);

        cur ^= 1;
        // Unconditional: r==15 writes pad pair 15 (finite garbage x zero weight).
        hbuf[wip][cur][ehalf][r] = pack2(t0, t1);
        __syncwarp();
    }

    // Epilogue: y[SEQ-1] from the final state (ym points at row SEQ-1).
    {
        const ulonglong2* __restrict__ hp =
            reinterpret_cast<const ulonglong2*>(&hbuf[wip][cur][ehalf][0]);
        u64 c0a = pack2(bias0, 0.f), c0b = 0ull;
        #pragma unroll
        for (int i = 0; i < 8; i++) {
            ulonglong2 hv = hp[i];
            c0a = fma2(hv.x, W0[2 * i],     c0a);
            c0b = fma2(hv.y, W0[2 * i + 1], c0b);
        }
        float u, v;
        unpack2(add2(c0a, c0b), u, v);
        st_pred(is_out, ym, u + v);
    }
}

extern "C" void kernel_launch(void* const* d_in, const int* in_sizes, int n_in,
                              void* d_out, int out_size) {
    const float* X     = (const float*)d_in[0];
    const float* W_ih  = (const float*)d_in[1];
    const float* W_hh  = (const float*)d_in[2];
    const float* b_ih  = (const float*)d_in[3];
    const float* b_hh  = (const float*)d_in[4];
    const float* W_out = (const float*)d_in[5];
    const float* b_out = (const float*)d_in[6];
    float* Y = (float*)d_out;

    // 2048 warps (2 elems each) in 128-thread blocks: 512 blocks over 148 SMs,
    // 4 warps/block -> one warp per SMSP per block (balanced schedulers).
    rnn_tanh_kernel<<<512, 128>>>(X, W_ih, W_hh, b_ih, b_hh, W_out, b_out, Y);
}